// round 9
// baseline (speedup 1.0000x reference)
#include <cuda_runtime.h>
#include <cstdint>
#include <cstddef>

#define NHEADS 32
#define HDIM 64
#define MBSZ 16
#define BDIM 4
#define LSEQ 2048
#define CDIM 2048
#define ODIM 768
#define NMB (LSEQ/MBSZ)
#define BL (BDIM*LSEQ)
#define EPSV 1e-6f

// -------- scratch (device globals; no allocations allowed) --------
__device__ float g_xqkv[(size_t)3*BL*CDIM];  // XQ | XK | XV, each [BL, C]
__device__ float g_lr[(size_t)BL*NHEADS];    // lr dot per (token, head)
__device__ float g_Y[(size_t)BL*CDIM];       // scan output, [B,L,C]
__device__ float g_YN[(size_t)BL*CDIM];      // post-norm output (tf32-rounded)
__device__ float g_Ht[(size_t)BL*CDIM];      // H rounded to tf32
__device__ float g_wt[(size_t)3*CDIM*CDIM];  // Wq^T | Wk^T | Wv^T  [N][K], tf32-rounded
__device__ float g_wot[(size_t)ODIM*CDIM];   // Wo^T [768][2048], tf32-rounded
__device__ unsigned g_done[64];              // per 128-row-block completion (24 CTAs each)

// ============================================================
// helpers
// ============================================================
__device__ __forceinline__ float totf32(float x){
  uint32_t u; asm("cvt.rna.tf32.f32 %0, %1;" : "=r"(u) : "f"(x));
  return __uint_as_float(u);
}
__device__ __forceinline__ void mma_tf32(float& d0, float& d1, float& d2, float& d3,
                                         uint32_t a0, uint32_t a1, uint32_t a2, uint32_t a3,
                                         uint32_t b0, uint32_t b1){
  asm volatile(
    "mma.sync.aligned.m16n8k8.row.col.f32.tf32.tf32.f32 "
    "{%0,%1,%2,%3}, {%4,%5,%6,%7}, {%8,%9}, {%0,%1,%2,%3};"
    : "+f"(d0), "+f"(d1), "+f"(d2), "+f"(d3)
    : "r"(a0), "r"(a1), "r"(a2), "r"(a3), "r"(b0), "r"(b1));
}
__device__ __forceinline__ uint32_t smem_u32(const void* p){
  uint32_t a;
  asm("{ .reg .u64 t; cvta.to.shared.u64 t, %1; cvt.u32.u64 %0, t; }" : "=r"(a) : "l"(p));
  return a;
}
__device__ __forceinline__ void cpa16(uint32_t dst, const void* src){
  asm volatile("cp.async.cg.shared.global [%0], [%1], 16;" :: "r"(dst), "l"(src));
}
__device__ __forceinline__ void cpa_commit(){
  asm volatile("cp.async.commit_group;" ::: "memory");
}

// SMEM tile geometry: row stride 36 floats (144B, 16B-aligned), K-chunk 32
#define TSTR 36
#define A_ST_B (128*TSTR*4)              // 18432 B per A stage
#define B_ST_B (256*TSTR*4)              // 36864 B per B stage
#define STG_B  (A_ST_B + B_ST_B)         // 55296 B per stage
#define NSTG 3
#define SM_GTOT (NSTG*STG_B)             // 165888 B

// ============================================================
// tf32 mma.sync GEMM body: C[M,Ntot] = A[M,2048] @ Bt[Ntot,2048]^T
// CTA tile 128x256, 8 warps (2 m x 4 n), warp tile 64x64
// ============================================================
__device__ __forceinline__ void gemm_tf32_body(
    const float* __restrict__ A, const float* __restrict__ Bt,
    float* __restrict__ C, int Ntot, int n0, int cRow)
{
  extern __shared__ float smem[];
  const uint32_t sb = smem_u32(smem);

  const int t    = threadIdx.x;
  const int wid  = t >> 5, lane = t & 31;
  const int wm   = wid & 1;
  const int wn   = wid >> 1;
  const int g    = lane >> 2;
  const int cc   = lane & 3;

  const int ldrow = t >> 3;
  const int ldc4  = t & 7;

  float d[4][8][4];
  #pragma unroll
  for (int mi=0;mi<4;mi++)
    #pragma unroll
    for (int ni=0;ni<8;ni++)
      #pragma unroll
      for (int r=0;r<4;r++) d[mi][ni][r]=0.f;

  auto issue = [&](int c2, int buf){
    const int k0 = c2*32;
    const uint32_t ab = sb + buf*STG_B;
    const uint32_t bb = ab + A_ST_B;
    #pragma unroll
    for (int it=0; it<4; it++){
      int row = ldrow + it*32;
      cpa16(ab + row*144 + ldc4*16,
            A + (size_t)(cRow+row)*CDIM + k0 + ldc4*4);
    }
    #pragma unroll
    for (int it=0; it<8; it++){
      int row = ldrow + it*32;
      cpa16(bb + row*144 + ldc4*16,
            Bt + (size_t)(n0+row)*CDIM + k0 + ldc4*4);
    }
    cpa_commit();
  };

  issue(0, 0);
  issue(1, 1);

  for (int c=0; c<64; c++){
    if (c==63) asm volatile("cp.async.wait_group 0;" ::: "memory");
    else       asm volatile("cp.async.wait_group 1;" ::: "memory");
    __syncthreads();
    if (c+2 < 64) issue(c+2, (c+2)%NSTG);

    const float* As = smem + (c%NSTG)*(STG_B/4);
    const float* Bs = As + (A_ST_B/4);
    #pragma unroll
    for (int ks=0; ks<4; ks++){
      const int kk = ks*8;
      uint32_t af[4][4];
      #pragma unroll
      for (int mi=0; mi<4; mi++){
        int r0 = wm*64 + mi*16;
        af[mi][0] = __float_as_uint(As[(r0 + g    )*TSTR + kk + cc    ]);
        af[mi][1] = __float_as_uint(As[(r0 + 8 + g)*TSTR + kk + cc    ]);
        af[mi][2] = __float_as_uint(As[(r0 + g    )*TSTR + kk + cc + 4]);
        af[mi][3] = __float_as_uint(As[(r0 + 8 + g)*TSTR + kk + cc + 4]);
      }
      uint32_t bf[8][2];
      #pragma unroll
      for (int ni=0; ni<8; ni++){
        int nr = wn*64 + ni*8 + g;
        bf[ni][0] = __float_as_uint(Bs[nr*TSTR + kk + cc    ]);
        bf[ni][1] = __float_as_uint(Bs[nr*TSTR + kk + cc + 4]);
      }
      #pragma unroll
      for (int mi=0; mi<4; mi++)
        #pragma unroll
        for (int ni=0; ni<8; ni++)
          mma_tf32(d[mi][ni][0], d[mi][ni][1], d[mi][ni][2], d[mi][ni][3],
                   af[mi][0], af[mi][1], af[mi][2], af[mi][3],
                   bf[ni][0], bf[ni][1]);
    }
  }

  #pragma unroll
  for (int mi=0; mi<4; mi++){
    int row = cRow + wm*64 + mi*16 + g;
    #pragma unroll
    for (int ni=0; ni<8; ni++){
      int col = n0 + wn*64 + ni*8 + cc*2;
      *(float2*)(C + (size_t)row*Ntot + col) =
          make_float2(d[mi][ni][0], d[mi][ni][1]);
      *(float2*)(C + (size_t)(row+8)*Ntot + col) =
          make_float2(d[mi][ni][2], d[mi][ni][3]);
    }
  }
}

// QKV: grid (24, 64): x = n(0..7) + 8*z(0..2); y = 128-row block.
// Publishes g_done[y] (24 arrivals per y) for the scan to consume.
__global__ __launch_bounds__(256,1) void gemm_qkv_tf32(){
  const int z = blockIdx.x >> 3;
  const int n = blockIdx.x & 7;
  const float* Bt = g_wt + (size_t)z * CDIM * CDIM;
  float* Cc = g_xqkv + (size_t)z * (size_t)BL * CDIM;
  gemm_tf32_body(g_Ht, Bt, Cc, CDIM, n*256, blockIdx.y*128);
  __threadfence();
  __syncthreads();
  if (threadIdx.x == 0) atomicAdd(&g_done[blockIdx.y], 1u);
}
__global__ __launch_bounds__(256,1) void gemm_out_tf32(float* __restrict__ out){
  gemm_tf32_body(g_YN, g_wot, out, ODIM, blockIdx.x*256, blockIdx.y*128);
}

__global__ void reset_done(){ if (threadIdx.x < 64) g_done[threadIdx.x] = 0u; }

// ============================================================
// transpose + tf32 round: in[R][C] -> out[C][R]
// ============================================================
__global__ __launch_bounds__(256) void transpose_k(
    const float* __restrict__ in, float* __restrict__ out, int R, int C)
{
  __shared__ float tile[32][33];
  int c0 = blockIdx.x*32, r0 = blockIdx.y*32;
  int tx = threadIdx.x & 31, ty = threadIdx.x >> 5;
  for (int i=ty; i<32; i+=8) tile[i][tx] = in[(size_t)(r0+i)*C + c0 + tx];
  __syncthreads();
  for (int i=ty; i<32; i+=8) out[(size_t)(c0+i)*R + r0 + tx] = totf32(tile[tx][i]);
}

__global__ __launch_bounds__(256) void round_tf32(const float* __restrict__ in){
  size_t i = ((size_t)blockIdx.x*256 + threadIdx.x)*4;
  float4 v = *(const float4*)(in + i);
  v.x=totf32(v.x); v.y=totf32(v.y); v.z=totf32(v.z); v.w=totf32(v.w);
  *(float4*)(g_Ht + i) = v;
}

// ============================================================
// lr dot: out[row, h] = sum_c X[row,c] * lrw[h,c]
// ============================================================
__global__ __launch_bounds__(256) void lr_gemm(
    const float* __restrict__ X, const float* __restrict__ Wl)
{
  __shared__ float Xs[64][65];
  __shared__ float Ws[64][33];
  int t = threadIdx.x;
  int row0 = blockIdx.x * 64;
  float acc[8];
  #pragma unroll
  for (int r=0;r<8;r++) acc[r]=0.f;
  int rBase = (t >> 5) * 8;
  int hCol  = t & 31;
  for (int k0=0;k0<CDIM;k0+=64){
    for (int e=t;e<1024;e+=256){
      int r = e >> 4; int c4 = (e & 15)*4;
      float4 v = *(const float4*)(X + (size_t)(row0+r)*CDIM + k0 + c4);
      Xs[r][c4+0]=v.x; Xs[r][c4+1]=v.y; Xs[r][c4+2]=v.z; Xs[r][c4+3]=v.w;
    }
    for (int e=t;e<512;e+=256){
      int hh = e >> 4; int c4 = (e & 15)*4;
      float4 v = *(const float4*)(Wl + (size_t)hh*CDIM + k0 + c4);
      Ws[c4+0][hh]=v.x; Ws[c4+1][hh]=v.y; Ws[c4+2][hh]=v.z; Ws[c4+3][hh]=v.w;
    }
    __syncthreads();
    #pragma unroll 16
    for (int k=0;k<64;k++){
      float w = Ws[k][hCol];
      #pragma unroll
      for (int r=0;r<8;r++) acc[r] = fmaf(Xs[rBase+r][k], w, acc[r]);
    }
    __syncthreads();
  }
  #pragma unroll
  for (int r=0;r<8;r++)
    g_lr[(size_t)(row0+rBase+r)*NHEADS + hCol] = acc[r];
}

// ============================================================
// TTT scan: one block per (b,h). 128 sequential mini-batch steps.
// Consumes g_done[y] flags so it can run concurrently with QKV.
// ============================================================
__global__ __launch_bounds__(256) void ttt_scan(
  const int*   __restrict__ pid,
  const float* __restrict__ W1in, const float* __restrict__ b1in,
  const float* __restrict__ lrb,  const float* __restrict__ ltid,
  const float* __restrict__ lnw,  const float* __restrict__ lnb)
{
  int b = blockIdx.x >> 5;
  int h = blockIdx.x & 31;
  __shared__ float W1s[64][65];
  __shared__ float b1s[64], gam[64], bet[64];
  __shared__ float xq[16][65], xk[16][65], xv[16][65], gr[16][65], zz[16][65];
  __shared__ float attn[16][16];
  __shared__ float etalr[16], ce[16], tok[16];
  __shared__ float ctab[16][32], stab[16][32];
  int t = threadIdx.x;

  for (int e=t;e<4096;e+=256) W1s[e>>6][e&63] = W1in[(size_t)h*4096 + e];
  if (t<64){ b1s[t]=b1in[h*64+t]; gam[t]=lnw[h*64+t]; bet[t]=lnb[h*64+t]; }
  if (t<16) tok[t] = fmaxf(1.f/(float)(t+1) + ltid[t], 0.f);
  for (int e=t;e<512;e+=256){
    int p = e >> 5, pi = e & 31;
    float inv = exp2f(-13.287712379549449f * (float)(2*pi) * (1.f/64.f));
    float ang = (float)p * inv;
    ctab[p][pi] = cosf(ang); stab[p][pi] = sinf(ang);
  }
  float lrbias = lrb[h];
  __syncthreads();

  const size_t PL = (size_t)BL*CDIM;
  const float* XQp = g_xqkv;
  const float* XKp = g_xqkv + PL;
  const float* XVp = g_xqkv + 2*PL;

  for (int m=0;m<NMB;m++){
    int l0 = m*MBSZ;
    // wait for producer row-block (8 minibatches per 128-row block)
    if ((m & 7) == 0){
      if (t == 0){
        int y = b*16 + (m >> 3);
        while (atomicAdd(&g_done[y], 0u) < 24u) __nanosleep(200);
      }
      __syncthreads();
      __threadfence();
    }
    for (int p=t;p<512;p+=256){
      int i = p >> 5, pi = p & 31;
      size_t base = ((size_t)b*LSEQ + l0 + i)*CDIM + h*64 + 2*pi;
      int pos = pid[(size_t)b*LSEQ + l0 + i] & 15;
      float c = ctab[pos][pi], s = stab[pos][pi];
      float q0=XQp[base], q1=XQp[base+1];
      xq[i][2*pi]   = q0*c - q1*s;
      xq[i][2*pi+1] = q1*c + q0*s;
      float k0=XKp[base], k1=XKp[base+1];
      xk[i][2*pi]   = k0*c - k1*s;
      xk[i][2*pi+1] = k1*c + k0*s;
    }
    for (int e=t;e<1024;e+=256){
      int i=e>>6, d=e&63;
      xv[i][d] = XVp[((size_t)b*LSEQ + l0 + i)*CDIM + h*64 + d];
    }
    if (t<16){
      float x = g_lr[((size_t)b*LSEQ + l0 + t)*NHEADS + h] + lrbias;
      float e = (1.f/(1.f+expf(-x))) * (1.f/64.f);
      etalr[t]=e; ce[t]=tok[15]*e;
    }
    __syncthreads();
    {
      int d = t & 63, i0 = t >> 6;
      for (int i=i0;i<16;i+=4){
        float a = b1s[d];
        #pragma unroll
        for (int k=0;k<64;k++) a = fmaf(xk[i][k], W1s[k][d], a);
        zz[i][d] = a;
      }
      int ai = t >> 4, aj = t & 15;
      float sdot = 0.f;
      if (aj <= ai){
        #pragma unroll
        for (int k=0;k<64;k++) sdot = fmaf(xq[ai][k], xk[aj][k], sdot);
      }
      attn[ai][aj] = sdot;
    }
    __syncthreads();
    {
      int w = t >> 5, lane = t & 31;
      for (int i=w;i<16;i+=8){
        float v0 = zz[i][lane], v1 = zz[i][lane+32];
        float sm = v0+v1, sq = v0*v0+v1*v1;
        #pragma unroll
        for (int o=16;o;o>>=1){ sm += __shfl_xor_sync(~0u, sm, o); sq += __shfl_xor_sync(~0u, sq, o); }
        float mu = sm * (1.f/64.f);
        float var = sq * (1.f/64.f) - mu*mu;
        float rstd = rsqrtf(var + EPSV);
        float xh0 = (v0-mu)*rstd, xh1 = (v1-mu)*rstd;
        float g0 = gam[lane], g1 = gam[lane+32];
        float y0 = g0*xh0 + bet[lane], y1 = g1*xh1 + bet[lane+32];
        float tg0 = (y0 - (xv[i][lane]    - xk[i][lane]   )) * g0;
        float tg1 = (y1 - (xv[i][lane+32] - xk[i][lane+32])) * g1;
        float sg = tg0+tg1, sgx = tg0*xh0 + tg1*xh1;
        #pragma unroll
        for (int o=16;o;o>>=1){ sg += __shfl_xor_sync(~0u, sg, o); sgx += __shfl_xor_sync(~0u, sgx, o); }
        float sc = rstd * (1.f/64.f);
        gr[i][lane]    = (64.f*tg0 - sg - xh0*sgx) * sc;
        gr[i][lane+32] = (64.f*tg1 - sg - xh1*sgx) * sc;
      }
    }
    __syncthreads();
    {
      int d = t & 63, i0 = t >> 6;
      for (int i=i0;i<16;i+=4){
        float a = b1s[d];
        #pragma unroll
        for (int k=0;k<64;k++) a = fmaf(xq[i][k], W1s[k][d], a);
        float ti = tok[i];
        for (int j=0;j<=i;j++){
          float cf = ti*etalr[j]*(attn[i][j] + 1.f);
          a = fmaf(-cf, gr[j][d], a);
        }
        zz[i][d] = a;
      }
    }
    __syncthreads();
    {
      int w = t >> 5, lane = t & 31;
      for (int i=w;i<16;i+=8){
        float v0 = zz[i][lane], v1 = zz[i][lane+32];
        float sm = v0+v1, sq = v0*v0+v1*v1;
        #pragma unroll
        for (int o=16;o;o>>=1){ sm += __shfl_xor_sync(~0u, sm, o); sq += __shfl_xor_sync(~0u, sq, o); }
        float mu = sm*(1.f/64.f);
        float rstd = rsqrtf(sq*(1.f/64.f) - mu*mu + EPSV);
        size_t orow = ((size_t)b*LSEQ + l0 + i)*CDIM + h*64;
        g_Y[orow+lane]    = xq[i][lane]    + gam[lane]   *((v0-mu)*rstd) + bet[lane];
        g_Y[orow+lane+32] = xq[i][lane+32] + gam[lane+32]*((v1-mu)*rstd) + bet[lane+32];
      }
      int k = t >> 2, d0 = (t & 3) * 16;
      float accw[16];
      #pragma unroll
      for (int dd=0;dd<16;dd++) accw[dd] = W1s[k][d0+dd];
      #pragma unroll
      for (int j=0;j<16;j++){
        float a = ce[j]*xk[j][k];
        #pragma unroll
        for (int dd=0;dd<16;dd++) accw[dd] = fmaf(-a, gr[j][d0+dd], accw[dd]);
      }
      #pragma unroll
      for (int dd=0;dd<16;dd++) W1s[k][d0+dd] = accw[dd];
      if (t<64){
        float a = b1s[t];
        #pragma unroll
        for (int j=0;j<16;j++) a = fmaf(-ce[j], gr[j][t], a);
        b1s[t] = a;
      }
    }
    __syncthreads();
  }
}

// ============================================================
// Post layernorm over C=2048 per row (output tf32-rounded for out-GEMM)
// ============================================================
__global__ __launch_bounds__(256) void rownorm(
    const float* __restrict__ w, const float* __restrict__ bias)
{
  int row = blockIdx.x; int t = threadIdx.x;
  const float* rp = g_Y + (size_t)row * CDIM;
  float s=0.f, ss=0.f;
  for (int c=t;c<CDIM;c+=256){ float v = rp[c]; s+=v; ss=fmaf(v,v,ss); }
  #pragma unroll
  for (int o=16;o;o>>=1){ s += __shfl_xor_sync(~0u,s,o); ss += __shfl_xor_sync(~0u,ss,o); }
  __shared__ float sw[8], ssw[8];
  int wid=t>>5, lane=t&31;
  if (lane==0){ sw[wid]=s; ssw[wid]=ss; }
  __syncthreads();
  float ts=0.f, tss=0.f;
  #pragma unroll
  for (int i2=0;i2<8;i2++){ ts+=sw[i2]; tss+=ssw[i2]; }
  float mu = ts*(1.f/CDIM);
  float rstd = rsqrtf(tss*(1.f/CDIM) - mu*mu + EPSV);
  float* op = g_YN + (size_t)row*CDIM;
  for (int c=t;c<CDIM;c+=256){
    float v=rp[c];
    op[c] = totf32((v-mu)*rstd*w[c] + bias[c]);
  }
}

// ============================================================
extern "C" void kernel_launch(void* const* d_in, const int* in_sizes, int n_in,
                              void* d_out, int out_size)
{
  const float* H   = (const float*)d_in[0];
  const int*   pid = (const int*)  d_in[1];
  const float* Wq  = (const float*)d_in[2];
  const float* Wk  = (const float*)d_in[3];
  const float* Wv  = (const float*)d_in[4];
  const float* Wo  = (const float*)d_in[5];
  const float* W1  = (const float*)d_in[6];
  const float* b1  = (const float*)d_in[7];
  const float* lrw = (const float*)d_in[8];
  const float* lrb = (const float*)d_in[9];
  const float* lti = (const float*)d_in[10];
  const float* lnw = (const float*)d_in[11];
  const float* lnb = (const float*)d_in[12];
  const float* pnw = (const float*)d_in[13];
  const float* pnb = (const float*)d_in[14];
  float* out = (float*)d_out;
  (void)in_sizes; (void)n_in; (void)out_size;

  static bool inited = false;
  static cudaStream_t s2;
  static cudaEvent_t evFork, evJoin;
  if (!inited){
    cudaFuncSetAttribute(gemm_qkv_tf32, cudaFuncAttributeMaxDynamicSharedMemorySize, SM_GTOT);
    cudaFuncSetAttribute(gemm_out_tf32, cudaFuncAttributeMaxDynamicSharedMemorySize, SM_GTOT);
    cudaStreamCreateWithFlags(&s2, cudaStreamNonBlocking);
    cudaEventCreateWithFlags(&evFork, cudaEventDisableTiming);
    cudaEventCreateWithFlags(&evJoin, cudaEventDisableTiming);
    inited = true;
  }

  float* wt0 = nullptr; cudaGetSymbolAddress((void**)&wt0, g_wt);
  float* wot = nullptr; cudaGetSymbolAddress((void**)&wot, g_wot);

  // s0: reset flags + prep
  reset_done<<<1, 64>>>();
  transpose_k<<<dim3(64,64), 256>>>(Wq, wt0,                         CDIM, CDIM);
  transpose_k<<<dim3(64,64), 256>>>(Wk, wt0 + (size_t)CDIM*CDIM,     CDIM, CDIM);
  transpose_k<<<dim3(64,64), 256>>>(Wv, wt0 + (size_t)2*CDIM*CDIM,   CDIM, CDIM);
  transpose_k<<<dim3(24,64), 256>>>(Wo, wot,                         CDIM, ODIM);
  round_tf32<<<(BL*(size_t)CDIM)/(256*4), 256>>>(H);

  // fork: scan pipeline on s2 (consumes QKV output via g_done flags)
  cudaEventRecord(evFork, 0);
  cudaStreamWaitEvent(s2, evFork, 0);
  lr_gemm<<<BL/64, 256, 0, s2>>>(H, lrw);
  ttt_scan<<<BDIM*NHEADS, 256, 0, s2>>>(pid, W1, b1, lrb, lti, lnw, lnb);
  cudaEventRecord(evJoin, s2);

  // s0: QKV GEMM runs concurrently with scan
  gemm_qkv_tf32<<<dim3(24, BL/128), 256, SM_GTOT>>>();

  // join, then post-norm + out projection
  cudaStreamWaitEvent(0, evJoin, 0);
  rownorm<<<BL, 256>>>(pnw, pnb);
  gemm_out_tf32<<<dim3(ODIM/256, BL/128), 256, SM_GTOT>>>(out);
}

// round 10
// speedup vs baseline: 1.5366x; 1.5366x over previous
#include <cuda_runtime.h>
#include <cstdint>
#include <cstddef>

#define NHEADS 32
#define HDIM 64
#define MBSZ 16
#define BDIM 4
#define LSEQ 2048
#define CDIM 2048
#define ODIM 768
#define NMB (LSEQ/MBSZ)
#define BL (BDIM*LSEQ)
#define EPSV 1e-6f

// -------- scratch (device globals; no allocations allowed) --------
__device__ float g_xqkv[(size_t)3*BL*CDIM];  // XQ | XK | XV, each [BL, C]
__device__ float g_lr[(size_t)BL*NHEADS];    // lr dot per (token, head)
__device__ float g_Y[(size_t)BL*CDIM];       // scan output, [B,L,C]
__device__ float g_YN[(size_t)BL*CDIM];      // post-norm output (tf32-rounded)
__device__ float g_Ht[(size_t)BL*CDIM];      // H rounded to tf32
__device__ float g_wt[(size_t)3*CDIM*CDIM];  // Wq^T | Wk^T | Wv^T  [N][K], tf32-rounded
__device__ float g_wot[(size_t)ODIM*CDIM];   // Wo^T [768][2048], tf32-rounded

// ============================================================
// helpers
// ============================================================
__device__ __forceinline__ float totf32(float x){
  uint32_t u; asm("cvt.rna.tf32.f32 %0, %1;" : "=r"(u) : "f"(x));
  return __uint_as_float(u);
}
__device__ __forceinline__ uint32_t tfu(float x){
  uint32_t u; asm("cvt.rna.tf32.f32 %0, %1;" : "=r"(u) : "f"(x));
  return u;
}
__device__ __forceinline__ void mma_tf32(float& d0, float& d1, float& d2, float& d3,
                                         uint32_t a0, uint32_t a1, uint32_t a2, uint32_t a3,
                                         uint32_t b0, uint32_t b1){
  asm volatile(
    "mma.sync.aligned.m16n8k8.row.col.f32.tf32.tf32.f32 "
    "{%0,%1,%2,%3}, {%4,%5,%6,%7}, {%8,%9}, {%0,%1,%2,%3};"
    : "+f"(d0), "+f"(d1), "+f"(d2), "+f"(d3)
    : "r"(a0), "r"(a1), "r"(a2), "r"(a3), "r"(b0), "r"(b1));
}
__device__ __forceinline__ uint32_t smem_u32(const void* p){
  uint32_t a;
  asm("{ .reg .u64 t; cvta.to.shared.u64 t, %1; cvt.u32.u64 %0, t; }" : "=r"(a) : "l"(p));
  return a;
}
__device__ __forceinline__ void cpa16(uint32_t dst, const void* src){
  asm volatile("cp.async.cg.shared.global [%0], [%1], 16;" :: "r"(dst), "l"(src));
}
__device__ __forceinline__ void cpa_commit(){
  asm volatile("cp.async.commit_group;" ::: "memory");
}

// SMEM tile geometry: row stride 36 floats (144B, 16B-aligned), K-chunk 32
#define TSTR 36
#define A_ST_B (128*TSTR*4)
#define B_ST_B (256*TSTR*4)
#define STG_B  (A_ST_B + B_ST_B)
#define NSTG 3
#define SM_GTOT (NSTG*STG_B)

// ============================================================
// tf32 mma.sync GEMM body: C[M,Ntot] = A[M,2048] @ Bt[Ntot,2048]^T
// CTA tile 128x256, 8 warps (2 m x 4 n), warp tile 64x64
// ============================================================
__device__ __forceinline__ void gemm_tf32_body(
    const float* __restrict__ A, const float* __restrict__ Bt,
    float* __restrict__ C, int Ntot, int n0, int cRow)
{
  extern __shared__ float smem[];
  const uint32_t sb = smem_u32(smem);

  const int t    = threadIdx.x;
  const int wid  = t >> 5, lane = t & 31;
  const int wm   = wid & 1;
  const int wn   = wid >> 1;
  const int g    = lane >> 2;
  const int cc   = lane & 3;

  const int ldrow = t >> 3;
  const int ldc4  = t & 7;

  float d[4][8][4];
  #pragma unroll
  for (int mi=0;mi<4;mi++)
    #pragma unroll
    for (int ni=0;ni<8;ni++)
      #pragma unroll
      for (int r=0;r<4;r++) d[mi][ni][r]=0.f;

  auto issue = [&](int c2, int buf){
    const int k0 = c2*32;
    const uint32_t ab = sb + buf*STG_B;
    const uint32_t bb = ab + A_ST_B;
    #pragma unroll
    for (int it=0; it<4; it++){
      int row = ldrow + it*32;
      cpa16(ab + row*144 + ldc4*16,
            A + (size_t)(cRow+row)*CDIM + k0 + ldc4*4);
    }
    #pragma unroll
    for (int it=0; it<8; it++){
      int row = ldrow + it*32;
      cpa16(bb + row*144 + ldc4*16,
            Bt + (size_t)(n0+row)*CDIM + k0 + ldc4*4);
    }
    cpa_commit();
  };

  issue(0, 0);
  issue(1, 1);

  for (int c=0; c<64; c++){
    if (c==63) asm volatile("cp.async.wait_group 0;" ::: "memory");
    else       asm volatile("cp.async.wait_group 1;" ::: "memory");
    __syncthreads();
    if (c+2 < 64) issue(c+2, (c+2)%NSTG);

    const float* As = smem + (c%NSTG)*(STG_B/4);
    const float* Bs = As + (A_ST_B/4);
    #pragma unroll
    for (int ks=0; ks<4; ks++){
      const int kk = ks*8;
      uint32_t af[4][4];
      #pragma unroll
      for (int mi=0; mi<4; mi++){
        int r0 = wm*64 + mi*16;
        af[mi][0] = __float_as_uint(As[(r0 + g    )*TSTR + kk + cc    ]);
        af[mi][1] = __float_as_uint(As[(r0 + 8 + g)*TSTR + kk + cc    ]);
        af[mi][2] = __float_as_uint(As[(r0 + g    )*TSTR + kk + cc + 4]);
        af[mi][3] = __float_as_uint(As[(r0 + 8 + g)*TSTR + kk + cc + 4]);
      }
      uint32_t bf[8][2];
      #pragma unroll
      for (int ni=0; ni<8; ni++){
        int nr = wn*64 + ni*8 + g;
        bf[ni][0] = __float_as_uint(Bs[nr*TSTR + kk + cc    ]);
        bf[ni][1] = __float_as_uint(Bs[nr*TSTR + kk + cc + 4]);
      }
      #pragma unroll
      for (int mi=0; mi<4; mi++)
        #pragma unroll
        for (int ni=0; ni<8; ni++)
          mma_tf32(d[mi][ni][0], d[mi][ni][1], d[mi][ni][2], d[mi][ni][3],
                   af[mi][0], af[mi][1], af[mi][2], af[mi][3],
                   bf[ni][0], bf[ni][1]);
    }
  }

  #pragma unroll
  for (int mi=0; mi<4; mi++){
    int row = cRow + wm*64 + mi*16 + g;
    #pragma unroll
    for (int ni=0; ni<8; ni++){
      int col = n0 + wn*64 + ni*8 + cc*2;
      *(float2*)(C + (size_t)row*Ntot + col) =
          make_float2(d[mi][ni][0], d[mi][ni][1]);
      *(float2*)(C + (size_t)(row+8)*Ntot + col) =
          make_float2(d[mi][ni][2], d[mi][ni][3]);
    }
  }
}

__global__ __launch_bounds__(256,1) void gemm_qkv_tf32(){
  const int z = blockIdx.x >> 3;
  const int n = blockIdx.x & 7;
  const float* Bt = g_wt + (size_t)z * CDIM * CDIM;
  float* Cc = g_xqkv + (size_t)z * (size_t)BL * CDIM;
  gemm_tf32_body(g_Ht, Bt, Cc, CDIM, n*256, blockIdx.y*128);
}
__global__ __launch_bounds__(256,1) void gemm_out_tf32(float* __restrict__ out){
  gemm_tf32_body(g_YN, g_wot, out, ODIM, blockIdx.x*256, blockIdx.y*128);
}

// ============================================================
// transpose + tf32 round: in[R][C] -> out[C][R]
// ============================================================
__global__ __launch_bounds__(256) void transpose_k(
    const float* __restrict__ in, float* __restrict__ out, int R, int C)
{
  __shared__ float tile[32][33];
  int c0 = blockIdx.x*32, r0 = blockIdx.y*32;
  int tx = threadIdx.x & 31, ty = threadIdx.x >> 5;
  for (int i=ty; i<32; i+=8) tile[i][tx] = in[(size_t)(r0+i)*C + c0 + tx];
  __syncthreads();
  for (int i=ty; i<32; i+=8) out[(size_t)(c0+i)*R + r0 + tx] = totf32(tile[tx][i]);
}

__global__ __launch_bounds__(256) void round_tf32(const float* __restrict__ in){
  size_t i = ((size_t)blockIdx.x*256 + threadIdx.x)*4;
  float4 v = *(const float4*)(in + i);
  v.x=totf32(v.x); v.y=totf32(v.y); v.z=totf32(v.z); v.w=totf32(v.w);
  *(float4*)(g_Ht + i) = v;
}

// ============================================================
// lr dot: out[row, h] = sum_c X[row,c] * lrw[h,c]
// ============================================================
__global__ __launch_bounds__(256) void lr_gemm(
    const float* __restrict__ X, const float* __restrict__ Wl)
{
  __shared__ float Xs[64][65];
  __shared__ float Ws[64][33];
  int t = threadIdx.x;
  int row0 = blockIdx.x * 64;
  float acc[8];
  #pragma unroll
  for (int r=0;r<8;r++) acc[r]=0.f;
  int rBase = (t >> 5) * 8;
  int hCol  = t & 31;
  for (int k0=0;k0<CDIM;k0+=64){
    for (int e=t;e<1024;e+=256){
      int r = e >> 4; int c4 = (e & 15)*4;
      float4 v = *(const float4*)(X + (size_t)(row0+r)*CDIM + k0 + c4);
      Xs[r][c4+0]=v.x; Xs[r][c4+1]=v.y; Xs[r][c4+2]=v.z; Xs[r][c4+3]=v.w;
    }
    for (int e=t;e<512;e+=256){
      int hh = e >> 4; int c4 = (e & 15)*4;
      float4 v = *(const float4*)(Wl + (size_t)hh*CDIM + k0 + c4);
      Ws[c4+0][hh]=v.x; Ws[c4+1][hh]=v.y; Ws[c4+2][hh]=v.z; Ws[c4+3][hh]=v.w;
    }
    __syncthreads();
    #pragma unroll 16
    for (int k=0;k<64;k++){
      float w = Ws[k][hCol];
      #pragma unroll
      for (int r=0;r<8;r++) acc[r] = fmaf(Xs[rBase+r][k], w, acc[r]);
    }
    __syncthreads();
  }
  #pragma unroll
  for (int r=0;r<8;r++)
    g_lr[(size_t)(row0+rBase+r)*NHEADS + hCol] = acc[r];
}

// ============================================================
// TTT scan: one block per (b,h). 128 sequential mini-batch steps.
// GEMM-lets (Z1, attn, Z1bar, W1-update) on mma.sync tf32 tensor cores.
// SMEM strides: g-row arrays (xq/xk/xv/zz) 68 -> banks 4g+cc distinct;
//               cc-row arrays (W1s/gr) 72 -> banks 8cc+g distinct; S 20.
// ============================================================
__global__ __launch_bounds__(256) void ttt_scan(
  const int*   __restrict__ pid,
  const float* __restrict__ W1in, const float* __restrict__ b1in,
  const float* __restrict__ lrb,  const float* __restrict__ ltid,
  const float* __restrict__ lnw,  const float* __restrict__ lnb)
{
  int b = blockIdx.x >> 5;
  int h = blockIdx.x & 31;
  __shared__ float W1s[64][72];
  __shared__ float gr[16][72];
  __shared__ float xq[16][68], xk[16][68], xv[16][68], zz[16][68];
  __shared__ float attn[16][20], Smat[16][20];
  __shared__ float b1s[64], gam[64], bet[64];
  __shared__ float etalr[16], ce[16], tok[16];
  __shared__ float ctab[16][32], stab[16][32];
  int t = threadIdx.x;
  int w = t >> 5, lane = t & 31;
  int g = lane >> 2, cc = lane & 3;

  for (int e=t;e<4096;e+=256) W1s[e>>6][e&63] = W1in[(size_t)h*4096 + e];
  if (t<64){ b1s[t]=b1in[h*64+t]; gam[t]=lnw[h*64+t]; bet[t]=lnb[h*64+t]; }
  if (t<16) tok[t] = fmaxf(1.f/(float)(t+1) + ltid[t], 0.f);
  for (int e=t;e<512;e+=256){
    int p = e >> 5, pi = e & 31;
    float inv = exp2f(-13.287712379549449f * (float)(2*pi) * (1.f/64.f));
    float ang = (float)p * inv;
    ctab[p][pi] = cosf(ang); stab[p][pi] = sinf(ang);
  }
  float lrbias = lrb[h];
  __syncthreads();

  const size_t PL = (size_t)BL*CDIM;
  const float* XQp = g_xqkv;
  const float* XKp = g_xqkv + PL;
  const float* XVp = g_xqkv + 2*PL;

  for (int m=0;m<NMB;m++){
    int l0 = m*MBSZ;
    // ---------- phase A: load + RoPE ----------
    for (int p=t;p<512;p+=256){
      int i = p >> 5, pi = p & 31;
      size_t base = ((size_t)b*LSEQ + l0 + i)*CDIM + h*64 + 2*pi;
      int pos = pid[(size_t)b*LSEQ + l0 + i] & 15;
      float c = ctab[pos][pi], s = stab[pos][pi];
      float q0=XQp[base], q1=XQp[base+1];
      xq[i][2*pi]   = q0*c - q1*s;
      xq[i][2*pi+1] = q1*c + q0*s;
      float k0=XKp[base], k1=XKp[base+1];
      xk[i][2*pi]   = k0*c - k1*s;
      xk[i][2*pi+1] = k1*c + k0*s;
    }
    for (int e=t;e<512;e+=256){
      int i = e >> 5, d2 = (e & 31)*2;
      float2 v = *(const float2*)(XVp + ((size_t)b*LSEQ + l0 + i)*CDIM + h*64 + d2);
      xv[i][d2] = v.x; xv[i][d2+1] = v.y;
    }
    if (t<16){
      float x = g_lr[((size_t)b*LSEQ + l0 + t)*NHEADS + h] + lrbias;
      float e = (1.f/(1.f+expf(-x))) * (1.f/64.f);
      etalr[t]=e; ce[t]=tok[15]*e;
    }
    __syncthreads();
    // ---------- phase B: Z1 = xk@W1 + b1 (mma); attn = xq@xk^T (mma, warps 0-1) ----------
    {
      const int n0 = w*8;
      float d0 = b1s[n0+2*cc], d1 = b1s[n0+2*cc+1];
      float d2 = d0, d3 = d1;
      #pragma unroll
      for (int ks=0; ks<8; ks++){
        const int kk = ks*8;
        uint32_t a0 = tfu(xk[g  ][kk+cc  ]), a1 = tfu(xk[8+g][kk+cc  ]);
        uint32_t a2 = tfu(xk[g  ][kk+cc+4]), a3 = tfu(xk[8+g][kk+cc+4]);
        uint32_t b0 = tfu(W1s[kk+cc][n0+g]), b1f= tfu(W1s[kk+cc+4][n0+g]);
        mma_tf32(d0,d1,d2,d3, a0,a1,a2,a3, b0,b1f);
      }
      zz[g  ][n0+2*cc]=d0; zz[g  ][n0+2*cc+1]=d1;
      zz[8+g][n0+2*cc]=d2; zz[8+g][n0+2*cc+1]=d3;
      if (w < 2){
        const int na = w*8;
        float e0=0.f,e1=0.f,e2=0.f,e3=0.f;
        #pragma unroll
        for (int ks=0; ks<8; ks++){
          const int kk = ks*8;
          uint32_t a0 = tfu(xq[g  ][kk+cc  ]), a1 = tfu(xq[8+g][kk+cc  ]);
          uint32_t a2 = tfu(xq[g  ][kk+cc+4]), a3 = tfu(xq[8+g][kk+cc+4]);
          uint32_t b0 = tfu(xk[na+g][kk+cc ]), b1f= tfu(xk[na+g][kk+cc+4]);
          mma_tf32(e0,e1,e2,e3, a0,a1,a2,a3, b0,b1f);
        }
        attn[g  ][na+2*cc]=e0; attn[g  ][na+2*cc+1]=e1;
        attn[8+g][na+2*cc]=e2; attn[8+g][na+2*cc+1]=e3;
      }
    }
    __syncthreads();
    // ---------- phase C: build S; grad = LN fused L2 bwd ----------
    {
      int i = t >> 4, j = t & 15;
      Smat[i][j] = (j <= i) ? -tok[i]*etalr[j]*(attn[i][j] + 1.f) : 0.f;
    }
    {
      for (int i=w;i<16;i+=8){
        float v0 = zz[i][lane], v1 = zz[i][lane+32];
        float sm = v0+v1, sq = v0*v0+v1*v1;
        #pragma unroll
        for (int o=16;o;o>>=1){ sm += __shfl_xor_sync(~0u, sm, o); sq += __shfl_xor_sync(~0u, sq, o); }
        float mu = sm * (1.f/64.f);
        float var = sq * (1.f/64.f) - mu*mu;
        float rstd = rsqrtf(var + EPSV);
        float xh0 = (v0-mu)*rstd, xh1 = (v1-mu)*rstd;
        float g0 = gam[lane], g1 = gam[lane+32];
        float y0 = g0*xh0 + bet[lane], y1 = g1*xh1 + bet[lane+32];
        float tg0 = (y0 - (xv[i][lane]    - xk[i][lane]   )) * g0;
        float tg1 = (y1 - (xv[i][lane+32] - xk[i][lane+32])) * g1;
        float sg = tg0+tg1, sgx = tg0*xh0 + tg1*xh1;
        #pragma unroll
        for (int o=16;o;o>>=1){ sg += __shfl_xor_sync(~0u, sg, o); sgx += __shfl_xor_sync(~0u, sgx, o); }
        float sc = rstd * (1.f/64.f);
        gr[i][lane]    = (64.f*tg0 - sg - xh0*sgx) * sc;
        gr[i][lane+32] = (64.f*tg1 - sg - xh1*sgx) * sc;
      }
    }
    __syncthreads();
    // ---------- phase D: Z1bar = xq@W1 + b1 + (-S)@gr (mma) ----------
    {
      const int n0 = w*8;
      float d0 = b1s[n0+2*cc], d1 = b1s[n0+2*cc+1];
      float d2 = d0, d3 = d1;
      #pragma unroll
      for (int ks=0; ks<8; ks++){
        const int kk = ks*8;
        uint32_t a0 = tfu(xq[g  ][kk+cc  ]), a1 = tfu(xq[8+g][kk+cc  ]);
        uint32_t a2 = tfu(xq[g  ][kk+cc+4]), a3 = tfu(xq[8+g][kk+cc+4]);
        uint32_t b0 = tfu(W1s[kk+cc][n0+g]), b1f= tfu(W1s[kk+cc+4][n0+g]);
        mma_tf32(d0,d1,d2,d3, a0,a1,a2,a3, b0,b1f);
      }
      #pragma unroll
      for (int ks=0; ks<2; ks++){
        const int kk = ks*8;
        uint32_t a0 = tfu(Smat[g  ][kk+cc  ]), a1 = tfu(Smat[8+g][kk+cc  ]);
        uint32_t a2 = tfu(Smat[g  ][kk+cc+4]), a3 = tfu(Smat[8+g][kk+cc+4]);
        uint32_t b0 = tfu(gr[kk+cc][n0+g]),   b1f= tfu(gr[kk+cc+4][n0+g]);
        mma_tf32(d0,d1,d2,d3, a0,a1,a2,a3, b0,b1f);
      }
      zz[g  ][n0+2*cc]=d0; zz[g  ][n0+2*cc+1]=d1;
      zz[8+g][n0+2*cc]=d2; zz[8+g][n0+2*cc+1]=d3;
    }
    __syncthreads();
    // ---------- phase E: out = xq + LN(Z1bar); W1,b1 update (mma) ----------
    {
      for (int i=w;i<16;i+=8){
        float v0 = zz[i][lane], v1 = zz[i][lane+32];
        float sm = v0+v1, sq = v0*v0+v1*v1;
        #pragma unroll
        for (int o=16;o;o>>=1){ sm += __shfl_xor_sync(~0u, sm, o); sq += __shfl_xor_sync(~0u, sq, o); }
        float mu = sm*(1.f/64.f);
        float rstd = rsqrtf(sq*(1.f/64.f) - mu*mu + EPSV);
        size_t orow = ((size_t)b*LSEQ + l0 + i)*CDIM + h*64;
        g_Y[orow+lane]    = xq[i][lane]    + gam[lane]   *((v0-mu)*rstd) + bet[lane];
        g_Y[orow+lane+32] = xq[i][lane+32] + gam[lane+32]*((v1-mu)*rstd) + bet[lane+32];
      }
      // W1 -= (ce*xk)^T @ gr : D = (-A)@B + W1
      const int m0 = 16*(w & 3);
      uint32_t ua[2][4];
      #pragma unroll
      for (int ks=0; ks<2; ks++){
        const int kk = ks*8;
        ua[ks][0] = tfu(-ce[kk+cc  ] * xk[kk+cc  ][m0+g  ]);
        ua[ks][1] = tfu(-ce[kk+cc  ] * xk[kk+cc  ][m0+8+g]);
        ua[ks][2] = tfu(-ce[kk+cc+4] * xk[kk+cc+4][m0+g  ]);
        ua[ks][3] = tfu(-ce[kk+cc+4] * xk[kk+cc+4][m0+8+g]);
      }
      #pragma unroll
      for (int nt=0; nt<4; nt++){
        const int nu = 32*(w>>2) + 8*nt;
        float d0 = W1s[m0+g  ][nu+2*cc], d1 = W1s[m0+g  ][nu+2*cc+1];
        float d2 = W1s[m0+8+g][nu+2*cc], d3 = W1s[m0+8+g][nu+2*cc+1];
        #pragma unroll
        for (int ks=0; ks<2; ks++){
          const int kk = ks*8;
          uint32_t b0 = tfu(gr[kk+cc][nu+g]), b1f = tfu(gr[kk+cc+4][nu+g]);
          mma_tf32(d0,d1,d2,d3, ua[ks][0],ua[ks][1],ua[ks][2],ua[ks][3], b0,b1f);
        }
        W1s[m0+g  ][nu+2*cc]=d0; W1s[m0+g  ][nu+2*cc+1]=d1;
        W1s[m0+8+g][nu+2*cc]=d2; W1s[m0+8+g][nu+2*cc+1]=d3;
      }
      if (t<64){
        float a = b1s[t];
        #pragma unroll
        for (int j=0;j<16;j++) a = fmaf(-ce[j], gr[j][t], a);
        b1s[t] = a;
      }
    }
    __syncthreads();
  }
}

// ============================================================
// Post layernorm over C=2048 per row (output tf32-rounded for out-GEMM)
// ============================================================
__global__ __launch_bounds__(256) void rownorm(
    const float* __restrict__ w, const float* __restrict__ bias)
{
  int row = blockIdx.x; int t = threadIdx.x;
  const float* rp = g_Y + (size_t)row * CDIM;
  float s=0.f, ss=0.f;
  for (int c=t;c<CDIM;c+=256){ float v = rp[c]; s+=v; ss=fmaf(v,v,ss); }
  #pragma unroll
  for (int o=16;o;o>>=1){ s += __shfl_xor_sync(~0u,s,o); ss += __shfl_xor_sync(~0u,ss,o); }
  __shared__ float sw[8], ssw[8];
  int wid=t>>5, lane=t&31;
  if (lane==0){ sw[wid]=s; ssw[wid]=ss; }
  __syncthreads();
  float ts=0.f, tss=0.f;
  #pragma unroll
  for (int i2=0;i2<8;i2++){ ts+=sw[i2]; tss+=ssw[i2]; }
  float mu = ts*(1.f/CDIM);
  float rstd = rsqrtf(tss*(1.f/CDIM) - mu*mu + EPSV);
  float* op = g_YN + (size_t)row*CDIM;
  for (int c=t;c<CDIM;c+=256){
    float v=rp[c];
    op[c] = totf32((v-mu)*rstd*w[c] + bias[c]);
  }
}

// ============================================================
extern "C" void kernel_launch(void* const* d_in, const int* in_sizes, int n_in,
                              void* d_out, int out_size)
{
  const float* H   = (const float*)d_in[0];
  const int*   pid = (const int*)  d_in[1];
  const float* Wq  = (const float*)d_in[2];
  const float* Wk  = (const float*)d_in[3];
  const float* Wv  = (const float*)d_in[4];
  const float* Wo  = (const float*)d_in[5];
  const float* W1  = (const float*)d_in[6];
  const float* b1  = (const float*)d_in[7];
  const float* lrw = (const float*)d_in[8];
  const float* lrb = (const float*)d_in[9];
  const float* lti = (const float*)d_in[10];
  const float* lnw = (const float*)d_in[11];
  const float* lnb = (const float*)d_in[12];
  const float* pnw = (const float*)d_in[13];
  const float* pnb = (const float*)d_in[14];
  float* out = (float*)d_out;
  (void)in_sizes; (void)n_in; (void)out_size;

  static bool attr_set = false;
  if (!attr_set){
    cudaFuncSetAttribute(gemm_qkv_tf32, cudaFuncAttributeMaxDynamicSharedMemorySize, SM_GTOT);
    cudaFuncSetAttribute(gemm_out_tf32, cudaFuncAttributeMaxDynamicSharedMemorySize, SM_GTOT);
    attr_set = true;
  }

  float* wt0 = nullptr; cudaGetSymbolAddress((void**)&wt0, g_wt);
  float* wot = nullptr; cudaGetSymbolAddress((void**)&wot, g_wot);

  transpose_k<<<dim3(64,64), 256>>>(Wq, wt0,                         CDIM, CDIM);
  transpose_k<<<dim3(64,64), 256>>>(Wk, wt0 + (size_t)CDIM*CDIM,     CDIM, CDIM);
  transpose_k<<<dim3(64,64), 256>>>(Wv, wt0 + (size_t)2*CDIM*CDIM,   CDIM, CDIM);
  transpose_k<<<dim3(24,64), 256>>>(Wo, wot,                         CDIM, ODIM);
  round_tf32<<<(BL*(size_t)CDIM)/(256*4), 256>>>(H);

  gemm_qkv_tf32<<<dim3(24, BL/128), 256, SM_GTOT>>>();
  lr_gemm<<<BL/64, 256>>>(H, lrw);
  ttt_scan<<<BDIM*NHEADS, 256>>>(pid, W1, b1, lrb, lti, lnw, lnb);
  rownorm<<<BL, 256>>>(pnw, pnb);
  gemm_out_tf32<<<dim3(ODIM/256, BL/128), 256, SM_GTOT>>>(out);
}